// round 6
// baseline (speedup 1.0000x reference)
#include <cuda_runtime.h>
#include <math.h>
#include <stdint.h>

#define TMAX       131072
#define NT         256          // timesteps per fk block == blockDim
#define THREADS    256
#define NBF_MAX    (TMAX / NT)  // 512
#define FLOOR_Y    (-0.93f)
#define GRAV       (-0.0018f)

#define NSTG       4
#define CHUNK      8192          // bytes per pipeline stage
#define DYN_SMEM   (NSTG * CHUNK)   // 32KB; + ~12.6KB static < 48KB default limit

// ---------------- scan state: (sum_x, sum_z, a, b) ----------------
// y-recurrence: root' = max(root + vy, FLOOR_Y - fmin) == f(x)=max(x+a,b)
// composition (L earlier, R later): (La+Ra, max(Lb+Ra, Rb)); x,z plain sums.
struct SState { float sx, sz, a, b; };

__device__ __forceinline__ SState s_identity() {
    SState s; s.sx = 0.f; s.sz = 0.f; s.a = 0.f; s.b = -INFINITY; return s;
}
__device__ __forceinline__ SState s_combine(SState l, SState r) {
    SState o;
    o.sx = l.sx + r.sx;
    o.sz = l.sz + r.sz;
    o.a  = l.a  + r.a;
    o.b  = fmaxf(l.b + r.a, r.b);
    return o;
}
__device__ __forceinline__ float4 to4(SState s)   { return make_float4(s.sx, s.sz, s.a, s.b); }
__device__ __forceinline__ SState from4(float4 f) { SState s; s.sx=f.x; s.sz=f.y; s.a=f.z; s.b=f.w; return s; }

// ---------------- lookback state (static device globals) ----------------
__device__ float4 g_aggVal[NBF_MAX];
__device__ float4 g_inclVal[NBF_MAX];
__device__ int    g_flag[NBF_MAX];      // 0 = invalid, 1 = aggregate, 2 = inclusive

// ---------------- PTX helpers ----------------
__device__ __forceinline__ uint32_t smem_u32(const void* p) {
    uint32_t a;
    asm("{ .reg .u64 t; cvta.to.shared.u64 t, %1; cvt.u32.u64 %0, t; }" : "=r"(a) : "l"(p));
    return a;
}
__device__ __forceinline__ void mbar_init(uint32_t mbar, uint32_t cnt) {
    asm volatile("mbarrier.init.shared.b64 [%0], %1;" :: "r"(mbar), "r"(cnt) : "memory");
}
__device__ __forceinline__ void mbar_expect_tx(uint32_t mbar, uint32_t bytes) {
    asm volatile("mbarrier.arrive.expect_tx.shared.b64 _, [%0], %1;" :: "r"(mbar), "r"(bytes) : "memory");
}
__device__ __forceinline__ void mbar_wait(uint32_t mbar, uint32_t parity) {
    asm volatile(
        "{\n\t"
        ".reg .pred P;\n\t"
        "LAB_%=:\n\t"
        "mbarrier.try_wait.parity.shared.b64 P, [%0], %1, 0x989680;\n\t"
        "@P bra.uni DONE_%=;\n\t"
        "bra.uni LAB_%=;\n\t"
        "DONE_%=:\n\t"
        "}" :: "r"(mbar), "r"(parity) : "memory");
}
__device__ __forceinline__ void bulk_g2s(uint32_t smemAddr, const void* gptr,
                                         uint32_t bytes, uint32_t mbar) {
    asm volatile(
        "cp.async.bulk.shared::cta.global.mbarrier::complete_tx::bytes [%0], [%1], %2, [%3];"
        :: "r"(smemAddr), "l"(gptr), "r"(bytes), "r"(mbar) : "memory");
}
__device__ __forceinline__ void bulk_s2g(void* gptr, uint32_t smemAddr, uint32_t bytes) {
    asm volatile(
        "cp.async.bulk.global.shared::cta.bulk_group [%0], [%1], %2;"
        :: "l"(gptr), "r"(smemAddr), "r"(bytes) : "memory");
}
#define BULK_COMMIT()     asm volatile("cp.async.bulk.commit_group;" ::: "memory")
#define BULK_WAIT_READ0() asm volatile("cp.async.bulk.wait_group.read 0;" ::: "memory")
#define BULK_WAIT_ALL()   asm volatile("cp.async.bulk.wait_group 0;" ::: "memory")
#define FENCE_ASYNC()     asm volatile("fence.proxy.async.shared::cta;" ::: "memory")

// ---------------- FK (vectorized loads) ----------------
__device__ __forceinline__ void mat_mul3(const float* A, const float* B, float* C) {
#pragma unroll
    for (int r = 0; r < 3; r++)
#pragma unroll
        for (int c = 0; c < 3; c++)
            C[r*3+c] = A[r*3+0]*B[0*3+c] + A[r*3+1]*B[1*3+c] + A[r*3+2]*B[2*3+c];
}
__device__ __forceinline__ void mat_vec_add3(const float* A, const float* v,
                                             const float* pin, float* pout) {
#pragma unroll
    for (int r = 0; r < 3; r++)
        pout[r] = pin[r] + A[r*3+0]*v[0] + A[r*3+1]*v[1] + A[r*3+2]*v[2];
}

// pose row = 216 floats. Needed float4 indices {0..6, 9..13, 15..20}.
// Slot offsets into M: s0=0, s1=9, s2=18, s3=36(j4), s4=45(j5), s5=63(j7), s6=72(j8).
// feet order FEET=[7,5,8,6]; fmin over p5..p8 y.
__device__ __forceinline__ void fk_feet(const float* __restrict__ row,
                                        const float* __restrict__ b,
                                        float* feet, float& fmin)
{
    const float4* __restrict__ q = (const float4*)row;
    float M[84];
#define LD4(i) *(float4*)&M[4*(i)] = q[(i)];
    LD4(0) LD4(1) LD4(2) LD4(3) LD4(4) LD4(5) LD4(6)
    LD4(9) LD4(10) LD4(11) LD4(12) LD4(13)
    LD4(15) LD4(16) LD4(17) LD4(18) LD4(19) LD4(20)
#undef LD4

    float R1[9], R2[9];
    float p0[3], pt[3];
#pragma unroll
    for (int i = 0; i < 3; i++) p0[i] = b[i];

    float p3_[3], p4_[3], p5_[3], p6_[3], p7_[3], p8_[3];

    // chain A: 0 -> 1 -> 3 -> 5 -> 7
    mat_vec_add3(M, b + 3, p0, pt);            // p1
    mat_mul3(M, M + 9, R1);                    // Rg1
    mat_vec_add3(R1, b + 9, pt, p3_);          // p3
    mat_mul3(R1, M + 36, R2);                  // Rg3
    mat_vec_add3(R2, b + 15, p3_, p5_);        // p5
    mat_mul3(R2, M + 63, R1);                  // Rg5
    mat_vec_add3(R1, b + 21, p5_, p7_);        // p7

    // chain B: 0 -> 2 -> 4 -> 6 -> 8
    mat_vec_add3(M, b + 6, p0, pt);            // p2
    mat_mul3(M, M + 18, R1);                   // Rg2
    mat_vec_add3(R1, b + 12, pt, p4_);         // p4
    mat_mul3(R1, M + 45, R2);                  // Rg4
    mat_vec_add3(R2, b + 18, p4_, p6_);        // p6
    mat_mul3(R2, M + 72, R1);                  // Rg6
    mat_vec_add3(R1, b + 24, p6_, p8_);        // p8

    feet[0] = p7_[0]; feet[1]  = p7_[1]; feet[2]  = p7_[2];
    feet[3] = p5_[0]; feet[4]  = p5_[1]; feet[5]  = p5_[2];
    feet[6] = p8_[0]; feet[7]  = p8_[1]; feet[8]  = p8_[2];
    feet[9] = p6_[0]; feet[10] = p6_[1]; feet[11] = p6_[2];
    fmin = fminf(fminf(p5_[1], p6_[1]), fminf(p7_[1], p8_[1]));
}

// ---------------- K0: reset lookback flags ----------------
__global__ void k0_reset(int nb)
{
    const int i = blockIdx.x * blockDim.x + threadIdx.x;
    if (i < nb) g_flag[i] = 0;
}

// ---------------- K1: DMA copy blocks + fk/scan/lookback blocks ----------------
// bid % 3 == 0 -> fk block (fkid = bid/3), others -> copy block.
__global__ void __launch_bounds__(THREADS, 4)
k1_mixed(const float* __restrict__ pose, const float* __restrict__ bone,
         const int* __restrict__ index, float* __restrict__ out,
         int T, int nbFK, int nbCopy)
{
    extern __shared__ __align__(128) char dynbuf[];   // NSTG * CHUNK copy staging
    const int tid = threadIdx.x;
    const int bid = blockIdx.x;

    if (bid % 3 != 0) {
        // ================= COPY BLOCK (cp.async.bulk DMA pipeline) =================
        if (tid != 0) return;
        const int cid = bid - (bid / 3 + 1);
        const size_t totB   = (size_t)T * 864;                       // bytes
        size_t chunkB = (totB + nbCopy - 1) / nbCopy;
        chunkB = (chunkB + 15) & ~(size_t)15;
        const size_t beg = (size_t)cid * chunkB;
        if (beg >= totB) return;
        const size_t end = (beg + chunkB < totB) ? beg + chunkB : totB;
        const uint32_t sz = (uint32_t)(end - beg);                   // multiple of 16

        const char* gsrc = (const char*)pose + beg;
        char*       gdst = (char*)out + beg;

        __shared__ __align__(8) uint64_t mbar_store[NSTG];
        const uint32_t buf0 = smem_u32(dynbuf);
        uint32_t mb[NSTG];
#pragma unroll
        for (int s = 0; s < NSTG; s++) {
            mb[s] = smem_u32(&mbar_store[s]);
            mbar_init(mb[s], 1);
        }
        FENCE_ASYNC();

        const int nchunks = (int)((sz + CHUNK - 1) / CHUNK);
        // prologue: fill pipeline
#pragma unroll
        for (int j = 0; j < NSTG; j++) {
            if (j < nchunks) {
                uint32_t off = (uint32_t)j * CHUNK;
                uint32_t n   = (sz - off < CHUNK) ? (sz - off) : CHUNK;
                mbar_expect_tx(mb[j], n);
                bulk_g2s(buf0 + j * CHUNK, gsrc + off, n, mb[j]);
            }
        }
        for (int c = 0; c < nchunks; c++) {
            const int b   = c % NSTG;
            const int par = (c / NSTG) & 1;
            mbar_wait(mb[b], par);
            uint32_t off = (uint32_t)c * CHUNK;
            uint32_t n   = (sz - off < CHUNK) ? (sz - off) : CHUNK;
            bulk_s2g(gdst + off, buf0 + b * CHUNK, n);
            BULK_COMMIT();
            const int nx = c + NSTG;
            if (nx < nchunks) {
                BULK_WAIT_READ0();    // stage b's smem drained -> reusable
                uint32_t off2 = (uint32_t)nx * CHUNK;
                uint32_t n2   = (sz - off2 < CHUNK) ? (sz - off2) : CHUNK;
                mbar_expect_tx(mb[b], n2);
                bulk_g2s(buf0 + b * CHUNK, gsrc + off2, n2, mb[b]);
            }
        }
        BULK_WAIT_ALL();              // ensure stores complete before block exit
        return;
    }

    // ================= FK / SCAN / LOOKBACK BLOCK =================
    const int fkid = bid / 3;
    if (fkid >= nbFK) return;

    __shared__ float  s_bone[27];
    __shared__ float  s_feet[(NT + 1) * 12];
    __shared__ float4 s_warp[THREADS / 32];
    __shared__ float4 s_aggSh, s_exclSh;

    const int t0 = fkid * NT;
    if (tid < 27) s_bone[tid] = bone[tid];

    const int t_mine = t0 + tid;
    int idx_mine = 0;
    if (t_mine < T) idx_mine = index[t_mine] & 3;
    __syncthreads();   // s_bone

    float      feetCur[12];
    float      fmin   = 0.f;
    const bool active = (t_mine < T);
    if (active) {
        fk_feet(pose + (size_t)t_mine * 216, s_bone, feetCur, fmin);
#pragma unroll
        for (int k = 0; k < 12; k++) s_feet[(tid + 1) * 12 + k] = feetCur[k];
    }
    if (tid == 0 && t0 > 0) {
        float fp[12]; float fd;
        fk_feet(pose + (size_t)(t0 - 1) * 216, s_bone, fp, fd);
#pragma unroll
        for (int k = 0; k < 12; k++) s_feet[k] = fp[k];
    }
    __syncthreads();

    SState v = s_identity();
    if (active) {
        float vx = 0.f, vy = GRAV, vz = 0.f;
        if (t_mine > 0) {
            vx =        s_feet[tid*12 + idx_mine*3 + 0] - feetCur[idx_mine*3 + 0];
            vy = GRAV + (s_feet[tid*12 + idx_mine*3 + 1] - feetCur[idx_mine*3 + 1]);
            vz =        s_feet[tid*12 + idx_mine*3 + 2] - feetCur[idx_mine*3 + 2];
        }
        v.sx = vx; v.sz = vz; v.a = vy; v.b = FLOOR_Y - fmin;
    }

    // ---- block-wide inclusive scan (8 warps) ----
    const int lane = tid & 31, warp = tid >> 5;
#pragma unroll
    for (int d = 1; d < 32; d <<= 1) {
        float osx = __shfl_up_sync(0xFFFFFFFFu, v.sx, d);
        float osz = __shfl_up_sync(0xFFFFFFFFu, v.sz, d);
        float oa  = __shfl_up_sync(0xFFFFFFFFu, v.a,  d);
        float ob  = __shfl_up_sync(0xFFFFFFFFu, v.b,  d);
        if (lane >= d) {
            SState o; o.sx = osx; o.sz = osz; o.a = oa; o.b = ob;
            v = s_combine(o, v);
        }
    }
    if (lane == 31) s_warp[warp] = to4(v);
    __syncthreads();
    if (warp == 0) {
        SState w = s_identity();
        if (lane < THREADS / 32) w = from4(s_warp[lane]);
#pragma unroll
        for (int d = 1; d < THREADS / 32; d <<= 1) {
            float osx = __shfl_up_sync(0xFFFFFFFFu, w.sx, d);
            float osz = __shfl_up_sync(0xFFFFFFFFu, w.sz, d);
            float oa  = __shfl_up_sync(0xFFFFFFFFu, w.a,  d);
            float ob  = __shfl_up_sync(0xFFFFFFFFu, w.b,  d);
            if (lane >= d) {
                SState o; o.sx = osx; o.sz = osz; o.a = oa; o.b = ob;
                w = s_combine(o, w);
            }
        }
        if (lane < THREADS / 32) s_warp[lane] = to4(w);
    }
    __syncthreads();
    if (warp > 0) v = s_combine(from4(s_warp[warp - 1]), v);

    // ---- publish aggregate / inclusive ----
    if (tid == THREADS - 1) {
        float4 a4 = to4(v);
        s_aggSh = a4;
        if (fkid == 0) {
            __stcg(&g_inclVal[0], a4);
            __threadfence();
            atomicExch(&g_flag[0], 2);
        } else {
            __stcg(&g_aggVal[fkid], a4);
            __threadfence();
            atomicExch(&g_flag[fkid], 1);
        }
    }
    if (fkid == 0 && tid == 0) s_exclSh = to4(s_identity());
    __syncthreads();

    // ---- decoupled lookback (warp 0), windowed 32 ----
    if (fkid > 0 && warp == 0) {
        SState excl = s_identity();
        int base = fkid - 1;
        for (;;) {
            const int j = base - lane;       // lane 0 = nearest predecessor
            SState val; int f;
            if (j < 0) { val = s_identity(); f = 2; }
            else {
                do {
                    f = __ldcg(&g_flag[j]);
                    if (f == 0) __nanosleep(40);
                } while (f == 0);
                __threadfence();
                float4 raw = (f == 2) ? __ldcg(&g_inclVal[j]) : __ldcg(&g_aggVal[j]);
                val = from4(raw);
            }
            const unsigned done = __ballot_sync(0xFFFFFFFFu, f == 2);
            const int L = done ? (__ffs(done) - 1) : 32;
            if (lane > L) val = s_identity();
            // ordered reduce: earlier blocks (higher lanes) on the LEFT
#pragma unroll
            for (int d = 1; d < 32; d <<= 1) {
                float osx = __shfl_down_sync(0xFFFFFFFFu, val.sx, d);
                float osz = __shfl_down_sync(0xFFFFFFFFu, val.sz, d);
                float oa  = __shfl_down_sync(0xFFFFFFFFu, val.a,  d);
                float ob  = __shfl_down_sync(0xFFFFFFFFu, val.b,  d);
                if (lane + d < 32) {
                    SState o; o.sx = osx; o.sz = osz; o.a = oa; o.b = ob;
                    val = s_combine(o, val);
                }
            }
            SState w;
            w.sx = __shfl_sync(0xFFFFFFFFu, val.sx, 0);
            w.sz = __shfl_sync(0xFFFFFFFFu, val.sz, 0);
            w.a  = __shfl_sync(0xFFFFFFFFu, val.a,  0);
            w.b  = __shfl_sync(0xFFFFFFFFu, val.b,  0);
            excl = s_combine(w, excl);
            if (done) break;
            base -= 32;
        }
        if (lane == 0) {
            SState incl = s_combine(excl, from4(s_aggSh));
            __stcg(&g_inclVal[fkid], to4(incl));
            __threadfence();
            atomicExch(&g_flag[fkid], 2);
            s_exclSh = to4(excl);
        }
    }
    __syncthreads();

    // ---- apply exclusive prefix, write trans directly ----
    if (active) {
        SState fin = s_combine(from4(s_exclSh), v);
        float* __restrict__ out_trans = out + (size_t)T * 216;
        out_trans[(size_t)t_mine * 3 + 0] = fin.sx;
        out_trans[(size_t)t_mine * 3 + 1] = fmaxf(fin.a, fin.b);
        out_trans[(size_t)t_mine * 3 + 2] = fin.sz;
    }
}

extern "C" void kernel_launch(void* const* d_in, const int* in_sizes, int n_in,
                              void* d_out, int out_size)
{
    const float* pose  = (const float*)d_in[0];   // (T,24,3,3) f32
    const float* bone  = (const float*)d_in[1];   // (9,3) f32
    const int*   index = (const int*)d_in[2];     // (T,) i32
    float*       out   = (float*)d_out;           // [pose | trans]

    const int T      = in_sizes[2];
    const int nbFK   = (T + NT - 1) / NT;
    const int nbCopy = 2 * nbFK;
    const int grid   = 3 * nbFK;                  // interleaved: bid%3==0 -> fk

    k0_reset<<<(nbFK + 255) / 256, 256>>>(nbFK);
    k1_mixed<<<grid, THREADS, DYN_SMEM>>>(pose, bone, index, out, T, nbFK, nbCopy);
}